// round 1
// baseline (speedup 1.0000x reference)
#include <cuda_runtime.h>
#include <math.h>

#define B_ROWS 8192
#define KNN    32
#define D      512

// 1/sqrt(512)
#define SCORE_SCALE 0.044194173824159220f

// -------- device scratch (allocation-free) --------
__device__ float g_W[D * D];          // w1^T @ w2   [d', d]
__device__ float g_c[D];              // b1 @ w2     [d]
__device__ float g_u[D];              // w1^T @ b2   [d]
__device__ float g_s0;                // b1 . b2
__device__ float g_q2[(size_t)B_ROWS * D];  // x @ W + c

// ============================================================
// Kernel 1: W[m,n] = sum_e w1[e,m] * w2[e,n]   (512x512x512)
// 64x64 tiles, BK=16, 256 threads, 4x4 per thread
// ============================================================
__global__ __launch_bounds__(256) void k_prep_W(const float* __restrict__ w1,
                                                const float* __restrict__ w2) {
    __shared__ __align__(16) float As[16][64];
    __shared__ __align__(16) float Bs[16][64];
    const int t  = threadIdx.x;
    const int tx = t & 15;
    const int ty = t >> 4;
    const int m0 = blockIdx.y * 64;
    const int n0 = blockIdx.x * 64;

    const int lr = t >> 4;         // 0..15 (k row within tile)
    const int lc = (t & 15) * 4;   // 0..60 (col4)

    float acc[4][4];
#pragma unroll
    for (int i = 0; i < 4; i++)
#pragma unroll
        for (int j = 0; j < 4; j++) acc[i][j] = 0.f;

    for (int k0 = 0; k0 < D; k0 += 16) {
        float4 a = *(const float4*)(w1 + (size_t)(k0 + lr) * D + m0 + lc);
        float4 b = *(const float4*)(w2 + (size_t)(k0 + lr) * D + n0 + lc);
        *(float4*)&As[lr][lc] = a;
        *(float4*)&Bs[lr][lc] = b;
        __syncthreads();
#pragma unroll
        for (int k = 0; k < 16; k++) {
            float ar[4], br[4];
#pragma unroll
            for (int i = 0; i < 4; i++) ar[i] = As[k][ty * 4 + i];
#pragma unroll
            for (int j = 0; j < 4; j++) br[j] = Bs[k][tx * 4 + j];
#pragma unroll
            for (int i = 0; i < 4; i++)
#pragma unroll
                for (int j = 0; j < 4; j++) acc[i][j] += ar[i] * br[j];
        }
        __syncthreads();
    }
#pragma unroll
    for (int i = 0; i < 4; i++) {
        float4 v = make_float4(acc[i][0], acc[i][1], acc[i][2], acc[i][3]);
        *(float4*)&g_W[(size_t)(m0 + ty * 4 + i) * D + n0 + tx * 4] = v;
    }
}

// ============================================================
// Kernel 2: c[d] = sum_e b1[e]*w2[e,d];  u[d] = sum_e b2[e]*w1[e,d];
//           s0 = b1.b2
// grid 4 x 128 threads
// ============================================================
__global__ void k_prep_aux(const float* __restrict__ w1,
                           const float* __restrict__ w2,
                           const float* __restrict__ b1,
                           const float* __restrict__ b2) {
    const int d = blockIdx.x * blockDim.x + threadIdx.x;
    float cacc = 0.f, uacc = 0.f;
    for (int e = 0; e < D; e++) {
        float b1e = b1[e];
        float b2e = b2[e];
        cacc += b1e * w2[(size_t)e * D + d];
        uacc += b2e * w1[(size_t)e * D + d];
    }
    g_c[d] = cacc;
    g_u[d] = uacc;
    if (blockIdx.x == 0 && threadIdx.x < 32) {
        float s = 0.f;
        for (int e = threadIdx.x; e < D; e += 32) s += b1[e] * b2[e];
#pragma unroll
        for (int o = 16; o; o >>= 1) s += __shfl_xor_sync(0xffffffffu, s, o);
        if (threadIdx.x == 0) g_s0 = s;
    }
}

// ============================================================
// Kernel 3: q2 = x @ W + c     (8192 x 512 x 512 SGEMM)
// BM=128 BN=128 BK=8, 256 threads, 8x8 per thread
// grid: (N/128=4, M/128=64)
// ============================================================
__global__ __launch_bounds__(256) void k_gemm_q2(const float* __restrict__ X) {
    __shared__ __align__(16) float As[8][128];
    __shared__ __align__(16) float Bs[8][128];
    const int t  = threadIdx.x;
    const int tx = t & 15;   // 0..15 -> col group
    const int ty = t >> 4;   // 0..15 -> row group
    const int bx = blockIdx.x;   // col tile (0..3)
    const int by = blockIdx.y;   // row tile (0..63)

    const int aRow  = t >> 1;          // 0..127
    const int aCol4 = (t & 1) * 4;     // 0 or 4
    const int bRow  = t >> 5;          // 0..7
    const int bCol4 = (t & 31) * 4;    // 0..124

    const float* Aptr = X + ((size_t)by * 128 + aRow) * D + aCol4;
    const float* Bptr = g_W + (size_t)bRow * D + bx * 128 + bCol4;

    float acc[8][8];
#pragma unroll
    for (int i = 0; i < 8; i++)
#pragma unroll
        for (int j = 0; j < 8; j++) acc[i][j] = 0.f;

    for (int k0 = 0; k0 < D; k0 += 8) {
        float4 av = *(const float4*)(Aptr + k0);
        float4 bv = *(const float4*)(Bptr + (size_t)k0 * D);
        As[aCol4 + 0][aRow] = av.x;
        As[aCol4 + 1][aRow] = av.y;
        As[aCol4 + 2][aRow] = av.z;
        As[aCol4 + 3][aRow] = av.w;
        *(float4*)&Bs[bRow][bCol4] = bv;
        __syncthreads();
#pragma unroll
        for (int k = 0; k < 8; k++) {
            float ar[8], br[8];
            *(float4*)&ar[0] = *(const float4*)&As[k][ty * 8];
            *(float4*)&ar[4] = *(const float4*)&As[k][ty * 8 + 4];
            *(float4*)&br[0] = *(const float4*)&Bs[k][tx * 8];
            *(float4*)&br[4] = *(const float4*)&Bs[k][tx * 8 + 4];
#pragma unroll
            for (int i = 0; i < 8; i++)
#pragma unroll
                for (int j = 0; j < 8; j++) acc[i][j] += ar[i] * br[j];
        }
        __syncthreads();
    }

    // epilogue: add c, store
    float cfr[8];
#pragma unroll
    for (int j = 0; j < 8; j++) cfr[j] = g_c[bx * 128 + tx * 8 + j];
#pragma unroll
    for (int i = 0; i < 8; i++) {
        const size_t row  = (size_t)by * 128 + ty * 8 + i;
        float* dst = g_q2 + row * D + bx * 128 + tx * 8;
        float4 v0 = make_float4(acc[i][0] + cfr[0], acc[i][1] + cfr[1],
                                acc[i][2] + cfr[2], acc[i][3] + cfr[3]);
        float4 v1 = make_float4(acc[i][4] + cfr[4], acc[i][5] + cfr[5],
                                acc[i][6] + cfr[6], acc[i][7] + cfr[7]);
        *(float4*)dst       = v0;
        *(float4*)(dst + 4) = v1;
    }
}

// ============================================================
// Kernel 4: per-row attention + blend.
// scores[k] = (q2[b].keys[b,k] + x[b].u + s0) / sqrt(D)
// out = 0.5*x + 0.5*softmax(scores) @ values[b]
// one block (256 threads) per row b
// ============================================================
__global__ __launch_bounds__(256) void k_attention(const float* __restrict__ x,
                                                   const float* __restrict__ keys,
                                                   const float* __restrict__ values,
                                                   float* __restrict__ out) {
    __shared__ __align__(16) float xs[D];
    __shared__ __align__(16) float q2s[D];
    __shared__ float att_s[KNN];
    __shared__ float warp_red[8];
    __shared__ float qb2_sh;

    const int b    = blockIdx.x;
    const int t    = threadIdx.x;
    const int lane = t & 31;
    const int w    = t >> 5;

    // load x row and q2 row to smem (128 float4 each, 256 threads total)
    if (t < 128) {
        ((float4*)xs)[t] = ((const float4*)(x + (size_t)b * D))[t];
    } else {
        ((float4*)q2s)[t - 128] = ((const float4*)(g_q2 + (size_t)b * D))[t - 128];
    }
    __syncthreads();

    // qb2 = x[b] . u + s0
    {
        float p = xs[t] * g_u[t] + xs[t + 256] * g_u[t + 256];
#pragma unroll
        for (int o = 16; o; o >>= 1) p += __shfl_xor_sync(0xffffffffu, p, o);
        if (lane == 0) warp_red[w] = p;
        __syncthreads();
        if (t == 0) {
            float s = 0.f;
#pragma unroll
            for (int i = 0; i < 8; i++) s += warp_red[i];
            qb2_sh = s + g_s0;
        }
        __syncthreads();
    }

    // scores: each warp handles 4 keys
    const float4* q2s4 = (const float4*)q2s;
    const float* kbase = keys + (size_t)b * KNN * D;
#pragma unroll
    for (int kk = 0; kk < 4; kk++) {
        const int k = w * 4 + kk;
        const float4* kr = (const float4*)(kbase + (size_t)k * D);
        float p = 0.f;
#pragma unroll
        for (int i = 0; i < 4; i++) {
            float4 kv = kr[lane + 32 * i];
            float4 qv = q2s4[lane + 32 * i];
            p += kv.x * qv.x + kv.y * qv.y + kv.z * qv.z + kv.w * qv.w;
        }
#pragma unroll
        for (int o = 16; o; o >>= 1) p += __shfl_xor_sync(0xffffffffu, p, o);
        if (lane == 0) att_s[k] = (p + qb2_sh) * SCORE_SCALE;
    }
    __syncthreads();

    // softmax over 32 scores (warp 0)
    if (t < 32) {
        float s = att_s[t];
        float m = s;
#pragma unroll
        for (int o = 16; o; o >>= 1) m = fmaxf(m, __shfl_xor_sync(0xffffffffu, m, o));
        float e = expf(s - m);
        float sum = e;
#pragma unroll
        for (int o = 16; o; o >>= 1) sum += __shfl_xor_sync(0xffffffffu, sum, o);
        att_s[t] = e / sum;
    }
    __syncthreads();

    // combined = att @ values[b]; out = 0.5*x + 0.5*combined
    const float* vbase = values + (size_t)b * KNN * D;
    float ax = 0.f, ay = 0.f;
#pragma unroll 4
    for (int k = 0; k < KNN; k++) {
        float a = att_s[k];
        float2 v = *(const float2*)(vbase + (size_t)k * D + 2 * t);
        ax += a * v.x;
        ay += a * v.y;
    }
    float2 xv = *(const float2*)&xs[2 * t];
    float2 o;
    o.x = 0.5f * xv.x + 0.5f * ax;
    o.y = 0.5f * xv.y + 0.5f * ay;
    *(float2*)(out + (size_t)b * D + 2 * t) = o;
}

// ============================================================
extern "C" void kernel_launch(void* const* d_in, const int* in_sizes, int n_in,
                              void* d_out, int out_size) {
    const float* x      = (const float*)d_in[0];
    const float* keys   = (const float*)d_in[1];
    const float* values = (const float*)d_in[2];
    const float* w1     = (const float*)d_in[3];
    // b1 = d_in[4], w2 = d_in[5], b2 = d_in[6]
    const float* b1     = (const float*)d_in[4];
    const float* w2     = (const float*)d_in[5];
    const float* b2     = (const float*)d_in[6];
    float* out          = (float*)d_out;

    (void)in_sizes; (void)n_in; (void)out_size;

    k_prep_W<<<dim3(8, 8), 256>>>(w1, w2);
    k_prep_aux<<<4, 128>>>(w1, w2, b1, b2);
    k_gemm_q2<<<dim3(4, 64), 256>>>(x);
    k_attention<<<B_ROWS, 256>>>(x, keys, values, out);
}